// round 16
// baseline (speedup 1.0000x reference)
#include <cuda_runtime.h>
#include <cuda_fp16.h>
#include <math.h>

// N=100000, E=1600000, D=OUT=128
#define MAX_N 100000
#define D_DIM 128
#define PAD_N 100096

// Scratch (device globals — allocation-free)
__device__ float  g_escore[MAX_N];              // exp(feature @ w_gate)
__device__ int    g_seg[MAX_N + 2];             // segment starts in sorted dst
__device__ __half g_G[(size_t)PAD_N * D_DIM];   // fp16(feature @ w_feat)
__device__ __half g_Wt[128 * 128];              // fp16 W^T (n-major, k contig)

// ---------------------------------------------------------------------------
// packed f32x2 helpers
// ---------------------------------------------------------------------------
__device__ __forceinline__ unsigned long long pack2(float lo, float hi) {
    unsigned long long r;
    asm("mov.b64 %0, {%1, %2};" : "=l"(r) : "f"(lo), "f"(hi));
    return r;
}
__device__ __forceinline__ unsigned long long dup2(float v) {
    unsigned long long r;
    asm("mov.b64 %0, {%1, %1};" : "=l"(r) : "f"(v));
    return r;
}
__device__ __forceinline__ void fma2(unsigned long long& d,
                                     unsigned long long a, unsigned long long b) {
    asm("fma.rn.f32x2 %0, %1, %2, %0;" : "+l"(d) : "l"(a), "l"(b));
}
__device__ __forceinline__ float2 unpack2(unsigned long long p) {
    float lo, hi;
    asm("mov.b64 {%0, %1}, %2;" : "=f"(lo), "=f"(hi) : "l"(p));
    return make_float2(lo, hi);
}

// ---------------------------------------------------------------------------
// k_wt: W transpose -> g_Wt fp16. WIDE: 64 blocks, 1 element per thread
//       (tiny grids pay a full serial memory round trip — R14 measured 4.7us
//       for the 4-block version; width hides the latency).
// ---------------------------------------------------------------------------
__global__ __launch_bounds__(256) void k_wt(const float* __restrict__ W)
{
    int idx = blockIdx.x * 256 + threadIdx.x;   // 0..16383
    int k = idx >> 7;
    int n = idx & 127;                          // consecutive threads -> coalesced load
    g_Wt[n * 128 + k] = __float2half(__ldg(W + k * 128 + n));
}

// ---------------------------------------------------------------------------
// KG: G = fp16(feature @ W) via HMMA + fused gate scores + segment-scan tail.
//     W^T pre-transposed in g_Wt (conflict-free smem copy). Epilogue through
//     smem -> coalesced STG.128. Tail: 8 dst edges per thread (2 x int4) —
//     runs in the already-resident GEMM blocks, so it hides in wave slack.
// ---------------------------------------------------------------------------
#define KG_PAD 136   // half-element smem row stride (272B, 16B-aligned)

__global__ __launch_bounds__(256) void kg_gemm(
    const float* __restrict__ feature,
    const float* __restrict__ w_gate,
    const int*   __restrict__ dst,
    int N, int E)
{
    extern __shared__ __half sh[];
    __half* Ah = sh;                     // [128][KG_PAD]  A tile / epilogue buf
    __half* Ws = sh + 128 * KG_PAD;      // [128][KG_PAD]  W^T (n-major)
    int tid = threadIdx.x;
    int lane = tid & 31;
    int row0 = blockIdx.x * 128;

    // Copy pre-transposed Wt: 2048 uint4, conflict-free
    #pragma unroll
    for (int q = tid; q < 2048; q += 256) {
        int r = q >> 4;
        int c = q & 15;
        *(uint4*)(Ws + r * KG_PAD + c * 8) = *(const uint4*)(g_Wt + r * 128 + c * 8);
    }

    // Load A tile; fused gate score per row.
    float4 g = ((const float4*)w_gate)[lane];
    #pragma unroll
    for (int q = tid; q < 128 * 32; q += 256) {
        int r  = q >> 5;
        int row = row0 + r;
        int rl = (row < N) ? row : (N - 1);
        float4 f = __ldg((const float4*)(feature + (size_t)rl * 128) + lane);
        __half2* p = (__half2*)(Ah + r * KG_PAD + lane * 4);
        p[0] = __floats2half2_rn(f.x, f.y);
        p[1] = __floats2half2_rn(f.z, f.w);
        float pv = f.x * g.x + f.y * g.y + f.z * g.z + f.w * g.w;
        #pragma unroll
        for (int o = 16; o; o >>= 1) pv += __shfl_xor_sync(0xFFFFFFFFu, pv, o);
        if (lane == 0 && row < N) g_escore[row] = expf(pv);
    }
    __syncthreads();

    int wid = tid >> 5;
    int warp_m = wid >> 1;          // 0..3
    int warp_n = wid & 1;           // 0..1
    int gid = lane >> 2;            // 0..7
    int tig = lane & 3;             // 0..3

    float c[2][8][4];
    #pragma unroll
    for (int mi = 0; mi < 2; ++mi)
        #pragma unroll
        for (int ni = 0; ni < 8; ++ni)
            #pragma unroll
            for (int x = 0; x < 4; ++x) c[mi][ni][x] = 0.f;

    #pragma unroll
    for (int k0 = 0; k0 < 128; k0 += 16) {
        unsigned a[2][4];
        #pragma unroll
        for (int mi = 0; mi < 2; ++mi) {
            const __half* base = Ah + (warp_m * 32 + mi * 16 + gid) * KG_PAD + k0 + tig * 2;
            a[mi][0] = *(const unsigned*)(base);
            a[mi][1] = *(const unsigned*)(base + 8 * KG_PAD);
            a[mi][2] = *(const unsigned*)(base + 8);
            a[mi][3] = *(const unsigned*)(base + 8 * KG_PAD + 8);
        }
        #pragma unroll
        for (int ni = 0; ni < 8; ++ni) {
            const __half* bb = Ws + (warp_n * 64 + ni * 8 + gid) * KG_PAD + k0 + tig * 2;
            unsigned b0 = *(const unsigned*)(bb);
            unsigned b1 = *(const unsigned*)(bb + 8);
            #pragma unroll
            for (int mi = 0; mi < 2; ++mi) {
                asm volatile(
                    "mma.sync.aligned.m16n8k16.row.col.f32.f16.f16.f32 "
                    "{%0,%1,%2,%3}, {%4,%5,%6,%7}, {%8,%9}, {%0,%1,%2,%3};"
                    : "+f"(c[mi][ni][0]), "+f"(c[mi][ni][1]),
                      "+f"(c[mi][ni][2]), "+f"(c[mi][ni][3])
                    : "r"(a[mi][0]), "r"(a[mi][1]), "r"(a[mi][2]), "r"(a[mi][3]),
                      "r"(b0), "r"(b1));
            }
        }
    }

    // Epilogue: fragments -> smem, then coalesced STG.128.
    __syncthreads();
    #pragma unroll
    for (int mi = 0; mi < 2; ++mi) {
        #pragma unroll
        for (int ni = 0; ni < 8; ++ni) {
            int m  = warp_m * 32 + mi * 16 + gid;
            int nn = warp_n * 64 + ni * 8 + tig * 2;
            *(__half2*)(Ah + m * KG_PAD + nn) =
                __floats2half2_rn(c[mi][ni][0], c[mi][ni][1]);
            *(__half2*)(Ah + (m + 8) * KG_PAD + nn) =
                __floats2half2_rn(c[mi][ni][2], c[mi][ni][3]);
        }
    }
    __syncthreads();
    #pragma unroll
    for (int q = tid; q < 2048; q += 256) {
        int r = q >> 4;
        int ch = q & 15;
        int row = row0 + r;
        if (row < N)
            *(uint4*)(g_G + (size_t)row * 128 + ch * 8) =
                *(const uint4*)(Ah + r * KG_PAD + ch * 8);
    }

    // ---- segment scan tail: 8 edges per thread (2 x int4) ----
    {
        int tidg = blockIdx.x * 256 + tid;
        int e0 = tidg * 8;
        if (e0 < E) {
            int prev = e0 ? __ldg(dst + e0 - 1) : -1;
            if (e0 + 8 <= E) {
                int4 d0 = __ldg((const int4*)(dst + e0));
                int4 d1 = __ldg((const int4*)(dst + e0 + 4));
                int vals[8] = {d0.x, d0.y, d0.z, d0.w, d1.x, d1.y, d1.z, d1.w};
                #pragma unroll
                for (int i = 0; i < 8; ++i) {
                    if (vals[i] != prev)
                        for (int n = prev + 1; n <= vals[i]; ++n) g_seg[n] = e0 + i;
                    prev = vals[i];
                }
            } else {
                for (int e = e0; e < E; ++e) {
                    int dc = __ldg(dst + e);
                    for (int n = prev + 1; n <= dc; ++n) g_seg[n] = e;
                    prev = dc;
                }
            }
            if (e0 + 8 >= E)
                for (int n = prev + 1; n <= N; ++n) g_seg[n] = E;
        }
    }
}

// ---------------------------------------------------------------------------
// K2: warp per node. Batch-prefetch 32 src/escore per lane, inner loop with
//     8 edges/iter (4 independent LDG.128, half-warp per edge row), packed
//     f32x2 accumulation. launch_bounds(256,6). (Frozen R13 config.)
// ---------------------------------------------------------------------------
__device__ __forceinline__ void accum8(unsigned long long* acc, float w, uint4 h) {
    unsigned long long wd = dup2(w);
    float2 f0 = __half22float2(*(__half2*)&h.x);
    float2 f1 = __half22float2(*(__half2*)&h.y);
    float2 f2 = __half22float2(*(__half2*)&h.z);
    float2 f3 = __half22float2(*(__half2*)&h.w);
    fma2(acc[0], wd, pack2(f0.x, f0.y));
    fma2(acc[1], wd, pack2(f1.x, f1.y));
    fma2(acc[2], wd, pack2(f2.x, f2.y));
    fma2(acc[3], wd, pack2(f3.x, f3.y));
}

__global__ __launch_bounds__(256, 6) void k2_out(
    const int* __restrict__ src,
    float* __restrict__ out,
    int N)
{
    int warp = (blockIdx.x * blockDim.x + threadIdx.x) >> 5;
    int lane = threadIdx.x & 31;
    if (warp >= N) return;

    int s = __ldg(g_seg + warp);
    int t = __ldg(g_seg + warp + 1);
    int hw  = lane >> 4;
    int l16 = lane & 15;

    unsigned long long acc[4] = {0ULL, 0ULL, 0ULL, 0ULL};
    float dsum = 0.f;

    for (int base = s; base < t; base += 32) {
        int e = base + lane;
        bool v = e < t;
        int   sv = v ? __ldg(src + e) : 0;
        float we = v ? __ldg(g_escore + sv) : 0.f;
        dsum += we;

        int cnt = min(32, t - base);
        int j = 0;
        for (; j + 8 <= cnt; j += 8) {
            int   sA = __shfl_sync(0xFFFFFFFFu, sv, j + hw);
            int   sB = __shfl_sync(0xFFFFFFFFu, sv, j + 2 + hw);
            int   sC = __shfl_sync(0xFFFFFFFFu, sv, j + 4 + hw);
            int   sD = __shfl_sync(0xFFFFFFFFu, sv, j + 6 + hw);
            float wA = __shfl_sync(0xFFFFFFFFu, we, j + hw);
            float wB = __shfl_sync(0xFFFFFFFFu, we, j + 2 + hw);
            float wC = __shfl_sync(0xFFFFFFFFu, we, j + 4 + hw);
            float wD = __shfl_sync(0xFFFFFFFFu, we, j + 6 + hw);
            uint4 hA = __ldg((const uint4*)(g_G + (size_t)sA * 128) + l16);
            uint4 hB = __ldg((const uint4*)(g_G + (size_t)sB * 128) + l16);
            uint4 hC = __ldg((const uint4*)(g_G + (size_t)sC * 128) + l16);
            uint4 hD = __ldg((const uint4*)(g_G + (size_t)sD * 128) + l16);
            accum8(acc, wA, hA);
            accum8(acc, wB, hB);
            accum8(acc, wC, hC);
            accum8(acc, wD, hD);
        }
        for (; j + 4 <= cnt; j += 4) {
            int   sA = __shfl_sync(0xFFFFFFFFu, sv, j + hw);
            int   sB = __shfl_sync(0xFFFFFFFFu, sv, j + 2 + hw);
            float wA = __shfl_sync(0xFFFFFFFFu, we, j + hw);
            float wB = __shfl_sync(0xFFFFFFFFu, we, j + 2 + hw);
            uint4 hA = __ldg((const uint4*)(g_G + (size_t)sA * 128) + l16);
            uint4 hB = __ldg((const uint4*)(g_G + (size_t)sB * 128) + l16);
            accum8(acc, wA, hA);
            accum8(acc, wB, hB);
        }
        for (; j < cnt; j += 2) {
            int take = j + hw;
            int idx  = (take < cnt) ? take : (cnt - 1);
            int   sA = __shfl_sync(0xFFFFFFFFu, sv, idx);
            float wA = __shfl_sync(0xFFFFFFFFu, we, idx);
            if (take >= cnt) wA = 0.f;
            uint4 hA = __ldg((const uint4*)(g_G + (size_t)sA * 128) + l16);
            accum8(acc, wA, hA);
        }
    }

    #pragma unroll
    for (int o = 16; o; o >>= 1) dsum += __shfl_xor_sync(0xFFFFFFFFu, dsum, o);

    float2 r[4];
    #pragma unroll
    for (int i = 0; i < 4; ++i) {
        r[i] = unpack2(acc[i]);
        r[i].x += __shfl_down_sync(0xFFFFFFFFu, r[i].x, 16);
        r[i].y += __shfl_down_sync(0xFFFFFFFFu, r[i].y, 16);
    }

    if (lane < 16) {
        float inv = (t > s) ? 1.f / dsum : 0.f;
        float* o = out + (size_t)warp * 128 + l16 * 8;
        *(float4*)(o)     = make_float4(r[0].x * inv, r[0].y * inv, r[1].x * inv, r[1].y * inv);
        *(float4*)(o + 4) = make_float4(r[2].x * inv, r[2].y * inv, r[3].x * inv, r[3].y * inv);
    }
}

// ---------------------------------------------------------------------------
extern "C" void kernel_launch(void* const* d_in, const int* in_sizes, int n_in,
                              void* d_out, int out_size)
{
    const float* feature = (const float*)d_in[0];
    const int*   src     = (const int*)  d_in[1];
    const int*   dst     = (const int*)  d_in[2];
    const float* w_gate  = (const float*)d_in[3];
    const float* w_feat  = (const float*)d_in[4];
    float*       out     = (float*)d_out;

    int N = in_sizes[0] / D_DIM;
    int E = in_sizes[1];

    const int SMEM_KG = 2 * 128 * KG_PAD * (int)sizeof(__half);   // 69,632 B
    cudaFuncSetAttribute(kg_gemm, cudaFuncAttributeMaxDynamicSharedMemorySize, SMEM_KG);

    // one-time W transpose (wide: 64 blocks, 1 element/thread)
    k_wt<<<64, 256>>>(w_feat);

    // G = fp16(feature @ w_feat) + fused escore + segment-scan tail
    int blocksG = (N + 127) / 128;   // 782 blocks * 256 thr * 8 edges >= E
    kg_gemm<<<blocksG, 256, SMEM_KG>>>(feature, w_gate, dst, N, E);

    // softmax-weighted gather of G -> out
    int blocks2 = (N * 32 + 255) / 256;
    k2_out<<<blocks2, 256>>>(src, out, N);
}

// round 17
// speedup vs baseline: 1.0887x; 1.0887x over previous
#include <cuda_runtime.h>
#include <cuda_fp16.h>
#include <math.h>

// N=100000, E=1600000, D=OUT=128
#define MAX_N 100000
#define D_DIM 128
#define PAD_N 100096

// Scratch (device globals — allocation-free)
__device__ float  g_escore[MAX_N];              // exp(feature @ w_gate)
__device__ int    g_seg[MAX_N + 2];             // segment starts in sorted dst
__device__ __half g_G[(size_t)PAD_N * D_DIM];   // fp16(feature @ w_feat)
__device__ __half g_Wt[128 * 128];              // fp16 W^T (n-major, k contig)

// ---------------------------------------------------------------------------
// packed f32x2 helpers
// ---------------------------------------------------------------------------
__device__ __forceinline__ unsigned long long pack2(float lo, float hi) {
    unsigned long long r;
    asm("mov.b64 %0, {%1, %2};" : "=l"(r) : "f"(lo), "f"(hi));
    return r;
}
__device__ __forceinline__ void add2(unsigned long long& d, unsigned long long a) {
    asm("add.rn.f32x2 %0, %0, %1;" : "+l"(d) : "l"(a));
}
__device__ __forceinline__ float2 unpack2(unsigned long long p) {
    float lo, hi;
    asm("mov.b64 {%0, %1}, %2;" : "=f"(lo), "=f"(hi) : "l"(p));
    return make_float2(lo, hi);
}

// ---------------------------------------------------------------------------
// k_seg_w: blocks [0, blocksS) scan segment boundaries, 4 edges per thread
//          (int4 loads). Blocks [blocksS, blocksS+4) transpose W -> g_Wt.
//          (Proven R13 front-end — trailing blocks avoid a separate launch.)
// ---------------------------------------------------------------------------
__global__ __launch_bounds__(256) void k_seg_w(
    const int*   __restrict__ dst,
    const float* __restrict__ W,
    int N, int E, int blocksS)
{
    if (blockIdx.x >= blocksS) {
        int extra = blockIdx.x - blocksS;           // 0..3
        int t = threadIdx.x;
        int n  = extra * 32 + (t >> 3);             // 0..127
        int k0 = (t & 7) * 16;                      // 0,16,...,112
        __half tmp[16];
        #pragma unroll
        for (int i = 0; i < 16; ++i)
            tmp[i] = __float2half(__ldg(W + (k0 + i) * 128 + n));
        #pragma unroll
        for (int i = 0; i < 2; ++i)
            *(uint4*)(g_Wt + n * 128 + k0 + i * 8) = *(uint4*)(tmp + i * 8);
        return;
    }

    int tidg = blockIdx.x * 256 + threadIdx.x;
    int e0 = tidg * 4;
    if (e0 >= E) return;
    int prev = e0 ? __ldg(dst + e0 - 1) : -1;
    if (e0 + 4 <= E) {
        int4 d = __ldg((const int4*)(dst + e0));
        if (d.x != prev) for (int n = prev + 1; n <= d.x; ++n) g_seg[n] = e0;
        if (d.y != d.x)  for (int n = d.x + 1;  n <= d.y; ++n) g_seg[n] = e0 + 1;
        if (d.z != d.y)  for (int n = d.y + 1;  n <= d.z; ++n) g_seg[n] = e0 + 2;
        if (d.w != d.z)  for (int n = d.z + 1;  n <= d.w; ++n) g_seg[n] = e0 + 3;
        prev = d.w;
    } else {
        for (int e = e0; e < E; ++e) {
            int dc = __ldg(dst + e);
            for (int n = prev + 1; n <= dc; ++n) g_seg[n] = e;
            prev = dc;
        }
    }
    if (e0 + 4 >= E) {
        for (int n = prev + 1; n <= N; ++n) g_seg[n] = E;
    }
}

// ---------------------------------------------------------------------------
// KG: G = fp16(feature @ W) via HMMA + fused gate scores. (Proven R13 config)
// ---------------------------------------------------------------------------
#define KG_PAD 136   // half-element smem row stride (272B, 16B-aligned)

__global__ __launch_bounds__(256) void kg_gemm(
    const float* __restrict__ feature,
    const float* __restrict__ w_gate,
    int N)
{
    extern __shared__ __half sh[];
    __half* Ah = sh;                     // [128][KG_PAD]  A tile / epilogue buf
    __half* Ws = sh + 128 * KG_PAD;      // [128][KG_PAD]  W^T (n-major)
    int tid = threadIdx.x;
    int lane = tid & 31;
    int row0 = blockIdx.x * 128;

    // Copy pre-transposed Wt: 2048 uint4, conflict-free
    #pragma unroll
    for (int q = tid; q < 2048; q += 256) {
        int r = q >> 4;
        int c = q & 15;
        *(uint4*)(Ws + r * KG_PAD + c * 8) = *(const uint4*)(g_Wt + r * 128 + c * 8);
    }

    // Load A tile; fused gate score per row.
    float4 g = ((const float4*)w_gate)[lane];
    #pragma unroll
    for (int q = tid; q < 128 * 32; q += 256) {
        int r  = q >> 5;
        int row = row0 + r;
        int rl = (row < N) ? row : (N - 1);
        float4 f = __ldg((const float4*)(feature + (size_t)rl * 128) + lane);
        __half2* p = (__half2*)(Ah + r * KG_PAD + lane * 4);
        p[0] = __floats2half2_rn(f.x, f.y);
        p[1] = __floats2half2_rn(f.z, f.w);
        float pv = f.x * g.x + f.y * g.y + f.z * g.z + f.w * g.w;
        #pragma unroll
        for (int o = 16; o; o >>= 1) pv += __shfl_xor_sync(0xFFFFFFFFu, pv, o);
        if (lane == 0 && row < N) g_escore[row] = expf(pv);
    }
    __syncthreads();

    int wid = tid >> 5;
    int warp_m = wid >> 1;
    int warp_n = wid & 1;
    int gid = lane >> 2;
    int tig = lane & 3;

    float c[2][8][4];
    #pragma unroll
    for (int mi = 0; mi < 2; ++mi)
        #pragma unroll
        for (int ni = 0; ni < 8; ++ni)
            #pragma unroll
            for (int x = 0; x < 4; ++x) c[mi][ni][x] = 0.f;

    #pragma unroll
    for (int k0 = 0; k0 < 128; k0 += 16) {
        unsigned a[2][4];
        #pragma unroll
        for (int mi = 0; mi < 2; ++mi) {
            const __half* base = Ah + (warp_m * 32 + mi * 16 + gid) * KG_PAD + k0 + tig * 2;
            a[mi][0] = *(const unsigned*)(base);
            a[mi][1] = *(const unsigned*)(base + 8 * KG_PAD);
            a[mi][2] = *(const unsigned*)(base + 8);
            a[mi][3] = *(const unsigned*)(base + 8 * KG_PAD + 8);
        }
        #pragma unroll
        for (int ni = 0; ni < 8; ++ni) {
            const __half* bb = Ws + (warp_n * 64 + ni * 8 + gid) * KG_PAD + k0 + tig * 2;
            unsigned b0 = *(const unsigned*)(bb);
            unsigned b1 = *(const unsigned*)(bb + 8);
            #pragma unroll
            for (int mi = 0; mi < 2; ++mi) {
                asm volatile(
                    "mma.sync.aligned.m16n8k16.row.col.f32.f16.f16.f32 "
                    "{%0,%1,%2,%3}, {%4,%5,%6,%7}, {%8,%9}, {%0,%1,%2,%3};"
                    : "+f"(c[mi][ni][0]), "+f"(c[mi][ni][1]),
                      "+f"(c[mi][ni][2]), "+f"(c[mi][ni][3])
                    : "r"(a[mi][0]), "r"(a[mi][1]), "r"(a[mi][2]), "r"(a[mi][3]),
                      "r"(b0), "r"(b1));
            }
        }
    }

    // Epilogue: fragments -> smem, then coalesced STG.128.
    __syncthreads();
    #pragma unroll
    for (int mi = 0; mi < 2; ++mi) {
        #pragma unroll
        for (int ni = 0; ni < 8; ++ni) {
            int m  = warp_m * 32 + mi * 16 + gid;
            int nn = warp_n * 64 + ni * 8 + tig * 2;
            *(__half2*)(Ah + m * KG_PAD + nn) =
                __floats2half2_rn(c[mi][ni][0], c[mi][ni][1]);
            *(__half2*)(Ah + (m + 8) * KG_PAD + nn) =
                __floats2half2_rn(c[mi][ni][2], c[mi][ni][3]);
        }
    }
    __syncthreads();
    #pragma unroll
    for (int q = tid; q < 2048; q += 256) {
        int r = q >> 4;
        int ch = q & 15;
        int row = row0 + r;
        if (row < N)
            *(uint4*)(g_G + (size_t)row * 128 + ch * 8) =
                *(const uint4*)(Ah + r * KG_PAD + ch * 8);
    }
}

// ---------------------------------------------------------------------------
// K2: warp per node, half-warp per edge row (R13 skeleton). NEW: weights
//     shfl'd pre-converted as half2; weight-multiply + 2-edge pair-sum in
//     fp16 (HMUL2/HFMA2), one convert+FADD2 per pair -> ~35% fewer
//     instructions per edge. dsum sums the ROUNDED weights (consistency).
// ---------------------------------------------------------------------------
__device__ __forceinline__ void accum_pair(unsigned long long* acc,
    unsigned wA2, uint4 hA, unsigned wB2, uint4 hB)
{
    __half2 wa = *(__half2*)&wA2, wb = *(__half2*)&wB2;
    __half2 t0 = __hfma2(*(__half2*)&hB.x, wb, __hmul2(*(__half2*)&hA.x, wa));
    __half2 t1 = __hfma2(*(__half2*)&hB.y, wb, __hmul2(*(__half2*)&hA.y, wa));
    __half2 t2 = __hfma2(*(__half2*)&hB.z, wb, __hmul2(*(__half2*)&hA.z, wa));
    __half2 t3 = __hfma2(*(__half2*)&hB.w, wb, __hmul2(*(__half2*)&hA.w, wa));
    float2 f0 = __half22float2(t0);
    float2 f1 = __half22float2(t1);
    float2 f2 = __half22float2(t2);
    float2 f3 = __half22float2(t3);
    add2(acc[0], pack2(f0.x, f0.y));
    add2(acc[1], pack2(f1.x, f1.y));
    add2(acc[2], pack2(f2.x, f2.y));
    add2(acc[3], pack2(f3.x, f3.y));
}

__device__ __forceinline__ void accum_one(unsigned long long* acc,
    unsigned wA2, uint4 hA)
{
    __half2 wa = *(__half2*)&wA2;
    __half2 t0 = __hmul2(*(__half2*)&hA.x, wa);
    __half2 t1 = __hmul2(*(__half2*)&hA.y, wa);
    __half2 t2 = __hmul2(*(__half2*)&hA.z, wa);
    __half2 t3 = __hmul2(*(__half2*)&hA.w, wa);
    float2 f0 = __half22float2(t0);
    float2 f1 = __half22float2(t1);
    float2 f2 = __half22float2(t2);
    float2 f3 = __half22float2(t3);
    add2(acc[0], pack2(f0.x, f0.y));
    add2(acc[1], pack2(f1.x, f1.y));
    add2(acc[2], pack2(f2.x, f2.y));
    add2(acc[3], pack2(f3.x, f3.y));
}

__global__ __launch_bounds__(256, 6) void k2_out(
    const int* __restrict__ src,
    float* __restrict__ out,
    int N)
{
    int warp = (blockIdx.x * blockDim.x + threadIdx.x) >> 5;
    int lane = threadIdx.x & 31;
    if (warp >= N) return;

    int s = __ldg(g_seg + warp);
    int t = __ldg(g_seg + warp + 1);
    int hw  = lane >> 4;
    int l16 = lane & 15;

    unsigned long long acc[4] = {0ULL, 0ULL, 0ULL, 0ULL};
    float dsum = 0.f;

    for (int base = s; base < t; base += 32) {
        // prefetch up to 32 edges: per-lane src + escore; convert weight to
        // half2 ONCE per lane (shfl carries the packed half2).
        int e = base + lane;
        bool v = e < t;
        int   sv = v ? __ldg(src + e) : 0;
        float weF = v ? __ldg(g_escore + sv) : 0.f;
        __half wh = __float2half_rn(weF);
        __half2 wh2h = __half2half2(wh);
        unsigned wh2 = *(unsigned*)&wh2h;
        dsum += __half2float(wh);          // rounded: consistent with numerator

        int cnt = min(32, t - base);
        int j = 0;
        for (; j + 8 <= cnt; j += 8) {
            int      sA = __shfl_sync(0xFFFFFFFFu, sv, j + hw);
            int      sB = __shfl_sync(0xFFFFFFFFu, sv, j + 2 + hw);
            int      sC = __shfl_sync(0xFFFFFFFFu, sv, j + 4 + hw);
            int      sD = __shfl_sync(0xFFFFFFFFu, sv, j + 6 + hw);
            unsigned wA = __shfl_sync(0xFFFFFFFFu, wh2, j + hw);
            unsigned wB = __shfl_sync(0xFFFFFFFFu, wh2, j + 2 + hw);
            unsigned wC = __shfl_sync(0xFFFFFFFFu, wh2, j + 4 + hw);
            unsigned wD = __shfl_sync(0xFFFFFFFFu, wh2, j + 6 + hw);
            uint4 hA = __ldg((const uint4*)(g_G + (size_t)sA * 128) + l16);
            uint4 hB = __ldg((const uint4*)(g_G + (size_t)sB * 128) + l16);
            uint4 hC = __ldg((const uint4*)(g_G + (size_t)sC * 128) + l16);
            uint4 hD = __ldg((const uint4*)(g_G + (size_t)sD * 128) + l16);
            accum_pair(acc, wA, hA, wB, hB);
            accum_pair(acc, wC, hC, wD, hD);
        }
        for (; j + 4 <= cnt; j += 4) {
            int      sA = __shfl_sync(0xFFFFFFFFu, sv, j + hw);
            int      sB = __shfl_sync(0xFFFFFFFFu, sv, j + 2 + hw);
            unsigned wA = __shfl_sync(0xFFFFFFFFu, wh2, j + hw);
            unsigned wB = __shfl_sync(0xFFFFFFFFu, wh2, j + 2 + hw);
            uint4 hA = __ldg((const uint4*)(g_G + (size_t)sA * 128) + l16);
            uint4 hB = __ldg((const uint4*)(g_G + (size_t)sB * 128) + l16);
            accum_pair(acc, wA, hA, wB, hB);
        }
        for (; j < cnt; j += 2) {
            int take = j + hw;
            int idx  = (take < cnt) ? take : (cnt - 1);
            int      sA = __shfl_sync(0xFFFFFFFFu, sv, idx);
            unsigned wA = __shfl_sync(0xFFFFFFFFu, wh2, idx);
            if (take >= cnt) wA = 0u;
            uint4 hA = __ldg((const uint4*)(g_G + (size_t)sA * 128) + l16);
            accum_one(acc, wA, hA);
        }
    }

    // full-warp dsum (each lane contributed distinct edges)
    #pragma unroll
    for (int o = 16; o; o >>= 1) dsum += __shfl_xor_sync(0xFFFFFFFFu, dsum, o);

    // combine the two half-warps
    float2 r[4];
    #pragma unroll
    for (int i = 0; i < 4; ++i) {
        r[i] = unpack2(acc[i]);
        r[i].x += __shfl_down_sync(0xFFFFFFFFu, r[i].x, 16);
        r[i].y += __shfl_down_sync(0xFFFFFFFFu, r[i].y, 16);
    }

    if (lane < 16) {
        float inv = (t > s) ? 1.f / dsum : 0.f;
        float* o = out + (size_t)warp * 128 + l16 * 8;
        *(float4*)(o)     = make_float4(r[0].x * inv, r[0].y * inv, r[1].x * inv, r[1].y * inv);
        *(float4*)(o + 4) = make_float4(r[2].x * inv, r[2].y * inv, r[3].x * inv, r[3].y * inv);
    }
}

// ---------------------------------------------------------------------------
extern "C" void kernel_launch(void* const* d_in, const int* in_sizes, int n_in,
                              void* d_out, int out_size)
{
    const float* feature = (const float*)d_in[0];
    const int*   src     = (const int*)  d_in[1];
    const int*   dst     = (const int*)  d_in[2];
    const float* w_gate  = (const float*)d_in[3];
    const float* w_feat  = (const float*)d_in[4];
    float*       out     = (float*)d_out;

    int N = in_sizes[0] / D_DIM;
    int E = in_sizes[1];

    const int SMEM_KG = 2 * 128 * KG_PAD * (int)sizeof(__half);   // 69,632 B
    cudaFuncSetAttribute(kg_gemm, cudaFuncAttributeMaxDynamicSharedMemorySize, SMEM_KG);

    // segment bounds (4 edges/thread) + one-time W transpose (trailing 4 blocks)
    int thr_seg = (E + 3) / 4;
    int blocksS = (thr_seg + 255) / 256;
    k_seg_w<<<blocksS + 4, 256>>>(dst, w_feat, N, E, blocksS);

    // G = fp16(feature @ w_feat) + fused escore
    int blocksG = (N + 127) / 128;
    kg_gemm<<<blocksG, 256, SMEM_KG>>>(feature, w_gate, N);

    // softmax-weighted gather of G -> out
    int blocks2 = (N * 32 + 255) / 256;
    k2_out<<<blocks2, 256>>>(src, out, N);
}